// round 1
// baseline (speedup 1.0000x reference)
#include <cuda_runtime.h>

// ---------------------------------------------------------------------------
// QWTForward: bicubic 2x downsample + 16 scaled copies.
//
//   D = downsample_bicubic(image)                 (4,16,256,256)
//   LL[b, g*16+c]        = D[b,c] * sLL[g]        (4,64,256,256)
//   H [b, g*16+c, band]  = D[b,c] * sH[band][g]   (4,64,3,256,256)
//
// Bicubic taps for scale=2 half-pixel: w = [-0.09375, 0.59375, 0.59375, -0.09375]
// applied at src offsets [-1,0,1,2] around 2*o, border-clamped.
// ---------------------------------------------------------------------------

#define B_    4
#define C_    16
#define HIN   512
#define WIN   512
#define HOUT  256
#define WOUT  256
#define PLANE (HOUT * WOUT)              // 65536
#define LL_TOTAL ((size_t)B_ * 64 * PLANE) // 16,777,216 floats

__device__ float g_scales[16];

__global__ void compute_scales_kernel(const float* __restrict__ gl,
                                      const float* __restrict__ gh,
                                      const float* __restrict__ fl,
                                      const float* __restrict__ fh) {
    if (threadIdx.x == 0) {
        float sg = 0.f, sh = 0.f, sfl = 0.f, sfh = 0.f;
        #pragma unroll
        for (int i = 0; i < 16; i++) {
            sg  += gl[i];
            sh  += gh[i];
            sfl += fl[i];
            sfh += fh[i];
        }
        // LL scales (g = 0..3)
        g_scales[0]  = sg  * sg;
        g_scales[1]  = sfl * sg;
        g_scales[2]  = sg  * sfl;
        g_scales[3]  = sfl * sfl;
        // band 1
        g_scales[4]  = sg  * sh;
        g_scales[5]  = sfl * sh;
        g_scales[6]  = sg  * sfh;
        g_scales[7]  = sfl * sfh;
        // band 2
        g_scales[8]  = sh  * sg;
        g_scales[9]  = sfh * sg;
        g_scales[10] = sh  * sfl;
        g_scales[11] = sfh * sfl;
        // band 3
        g_scales[12] = sh  * sh;
        g_scales[13] = sfh * sh;
        g_scales[14] = sh  * sfh;
        g_scales[15] = sfh * sfh;
    }
}

__global__ __launch_bounds__(256)
void qwt_kernel(const float* __restrict__ image, float* __restrict__ out) {
    __shared__ float sc[16];
    if (threadIdx.x < 16) sc[threadIdx.x] = g_scales[threadIdx.x];
    __syncthreads();

    // Linear thread id -> (b, c, y, x4); x4 selects 4 consecutive output x.
    unsigned tid = blockIdx.x * blockDim.x + threadIdx.x;
    int x4 = tid & 63;          // 64 float4 per row
    int y  = (tid >> 6) & 255;
    int c  = (tid >> 14) & 15;
    int b  = tid >> 18;

    const float w0 = -0.09375f, w1 = 0.59375f, w2 = 0.59375f, w3 = -0.09375f;

    const float* __restrict__ plane = image + (size_t)(b * C_ + c) * (HIN * WIN);

    // Input rows (clamped)
    int ry[4];
    #pragma unroll
    for (int i = 0; i < 4; i++) {
        int r = 2 * y - 1 + i;
        ry[i] = min(max(r, 0), HIN - 1);
    }
    // Input cols (clamped): need cols 8*x4-1 .. 8*x4+8
    int cx[10];
    #pragma unroll
    for (int k = 0; k < 10; k++) {
        int col = 8 * x4 - 1 + k;
        cx[k] = min(max(col, 0), WIN - 1);
    }

    // Horizontal then vertical convolution
    float d0 = 0.f, d1 = 0.f, d2 = 0.f, d3 = 0.f;
    const float wv[4] = {w0, w1, w2, w3};
    #pragma unroll
    for (int i = 0; i < 4; i++) {
        const float* __restrict__ row = plane + (size_t)ry[i] * WIN;
        float v[10];
        #pragma unroll
        for (int k = 0; k < 10; k++) v[k] = __ldg(row + cx[k]);
        float h0 = w0 * v[0] + w1 * v[1] + w2 * v[2] + w3 * v[3];
        float h1 = w0 * v[2] + w1 * v[3] + w2 * v[4] + w3 * v[5];
        float h2 = w0 * v[4] + w1 * v[5] + w2 * v[6] + w3 * v[7];
        float h3 = w0 * v[6] + w1 * v[7] + w2 * v[8] + w3 * v[9];
        float wi = wv[i];
        d0 = fmaf(wi, h0, d0);
        d1 = fmaf(wi, h1, d1);
        d2 = fmaf(wi, h2, d2);
        d3 = fmaf(wi, h3, d3);
    }

    size_t p = (size_t)y * WOUT + (size_t)x4 * 4;   // float4-aligned pixel offset

    // LL: out[(b*64 + g*16 + c)*PLANE + p]
    // H : out[LL_TOTAL + ((b*64 + g*16 + c)*3 + band)*PLANE + p]
    #pragma unroll
    for (int g = 0; g < 4; g++) {
        size_t ch = (size_t)(b * 64 + g * 16 + c);
        {
            float s = sc[g];
            float4 o = make_float4(d0 * s, d1 * s, d2 * s, d3 * s);
            *reinterpret_cast<float4*>(out + ch * PLANE + p) = o;
        }
        #pragma unroll
        for (int band = 0; band < 3; band++) {
            float s = sc[4 + band * 4 + g];
            float4 o = make_float4(d0 * s, d1 * s, d2 * s, d3 * s);
            *reinterpret_cast<float4*>(out + LL_TOTAL + (ch * 3 + band) * PLANE + p) = o;
        }
    }
}

extern "C" void kernel_launch(void* const* d_in, const int* in_sizes, int n_in,
                              void* d_out, int out_size) {
    const float* image = (const float*)d_in[0];
    const float* gl    = (const float*)d_in[1];
    const float* gh    = (const float*)d_in[2];
    const float* fl    = (const float*)d_in[3];
    const float* fh    = (const float*)d_in[4];
    float* out = (float*)d_out;

    compute_scales_kernel<<<1, 32>>>(gl, gh, fl, fh);

    // total threads = B*C*HOUT*(WOUT/4) = 4*16*256*64 = 1,048,576
    const int threads = 256;
    const int blocks = (B_ * C_ * HOUT * (WOUT / 4)) / threads;  // 4096
    qwt_kernel<<<blocks, threads>>>(image, out);
}

// round 3
// speedup vs baseline: 1.1350x; 1.1350x over previous
#include <cuda_runtime.h>

// ---------------------------------------------------------------------------
// QWTForward: bicubic 2x downsample + 16 scaled copies.
//
//   D = downsample_bicubic(image)                 (4,16,256,256)
//   LL[b, g*16+c]        = D[b,c] * sLL[g]        (4,64,256,256)
//   H [b, g*16+c, band]  = D[b,c] * sH[band][g]   (4,64,3,256,256)
//
// R2: vectorized float4 input loads + warp-shuffle halo exchange.
// ---------------------------------------------------------------------------

#define B_    4
#define C_    16
#define HIN   512
#define WIN   512
#define HOUT  256
#define WOUT  256
#define PLANE (HOUT * WOUT)                // 65536
#define LL_TOTAL ((size_t)B_ * 64 * PLANE) // 16,777,216 floats

__device__ float g_scales[16];

__global__ void compute_scales_kernel(const float* __restrict__ gl,
                                      const float* __restrict__ gh,
                                      const float* __restrict__ fl,
                                      const float* __restrict__ fh) {
    if (threadIdx.x == 0) {
        float sg = 0.f, sh = 0.f, sfl = 0.f, sfh = 0.f;
        #pragma unroll
        for (int i = 0; i < 16; i++) {
            sg  += gl[i];
            sh  += gh[i];
            sfl += fl[i];
            sfh += fh[i];
        }
        g_scales[0]  = sg  * sg;
        g_scales[1]  = sfl * sg;
        g_scales[2]  = sg  * sfl;
        g_scales[3]  = sfl * sfl;
        g_scales[4]  = sg  * sh;
        g_scales[5]  = sfl * sh;
        g_scales[6]  = sg  * sfh;
        g_scales[7]  = sfl * sfh;
        g_scales[8]  = sh  * sg;
        g_scales[9]  = sfh * sg;
        g_scales[10] = sh  * sfl;
        g_scales[11] = sfh * sfl;
        g_scales[12] = sh  * sh;
        g_scales[13] = sfh * sh;
        g_scales[14] = sh  * sfh;
        g_scales[15] = sfh * sfh;
    }
}

__global__ __launch_bounds__(256)
void qwt_kernel(const float* __restrict__ image, float* __restrict__ out) {
    __shared__ float sc[16];
    if (threadIdx.x < 16) sc[threadIdx.x] = g_scales[threadIdx.x];
    __syncthreads();

    // Linear thread id -> (b, c, y, x4); x4 selects 4 consecutive output x.
    unsigned tid = blockIdx.x * blockDim.x + threadIdx.x;
    int lane = threadIdx.x & 31;
    int x4 = tid & 63;          // 64 float4 per output row; consecutive within warp
    int y  = (tid >> 6) & 255;
    int c  = (tid >> 14) & 15;
    int b  = tid >> 18;

    const float w0 = -0.09375f, w1 = 0.59375f, w2 = 0.59375f, w3 = -0.09375f;
    const float wv[4] = {w0, w1, w2, w3};

    const float* __restrict__ plane = image + (size_t)(b * C_ + c) * (HIN * WIN);

    // Input rows (clamped)
    int ry[4];
    #pragma unroll
    for (int i = 0; i < 4; i++) {
        int r = 2 * y - 1 + i;
        ry[i] = min(max(r, 0), HIN - 1);
    }

    const int base = 8 * x4;                  // first input col of this thread's span
    // Halo source classification (uniform per thread across all rows):
    const bool left_clamp   = (x4 == 0);      // col -1 -> col 0
    const bool left_shfl    = (!left_clamp) && (lane > 0);
    const bool right_clamp  = (x4 == 63);     // col 512 -> col 511
    const bool right_shfl   = (!right_clamp) && (lane < 31);

    float d0 = 0.f, d1 = 0.f, d2 = 0.f, d3 = 0.f;

    #pragma unroll
    for (int i = 0; i < 4; i++) {
        const float* __restrict__ row = plane + (size_t)ry[i] * WIN;
        const float4* __restrict__ row4 = reinterpret_cast<const float4*>(row);
        float4 bv = __ldg(row4 + 2 * x4);       // cols base .. base+3
        float4 cv = __ldg(row4 + 2 * x4 + 1);   // cols base+4 .. base+7

        // Halo: col base-1 (prev lane's cv.w) and col base+8 (next lane's bv.x)
        float up = __shfl_up_sync(0xffffffffu, cv.w, 1);
        float dn = __shfl_down_sync(0xffffffffu, bv.x, 1);
        float vm1, vp8;
        if (left_clamp)       vm1 = bv.x;
        else if (left_shfl)   vm1 = up;
        else                  vm1 = __ldg(row + base - 1);   // lane 0 mid-row
        if (right_clamp)      vp8 = cv.w;
        else if (right_shfl)  vp8 = dn;
        else                  vp8 = __ldg(row + base + 8);   // lane 31 mid-row

        // Horizontal 4-tap at output cols 4*x4 + {0,1,2,3}
        float h0 = w0 * vm1  + w1 * bv.x + w2 * bv.y + w3 * bv.z;
        float h1 = w0 * bv.y + w1 * bv.z + w2 * bv.w + w3 * cv.x;
        float h2 = w0 * bv.w + w1 * cv.x + w2 * cv.y + w3 * cv.z;
        float h3 = w0 * cv.y + w1 * cv.z + w2 * cv.w + w3 * vp8;

        float wi = wv[i];
        d0 = fmaf(wi, h0, d0);
        d1 = fmaf(wi, h1, d1);
        d2 = fmaf(wi, h2, d2);
        d3 = fmaf(wi, h3, d3);
    }

    size_t p = (size_t)y * WOUT + (size_t)x4 * 4;   // float4-aligned pixel offset

    // LL: out[(b*64 + g*16 + c)*PLANE + p]
    // H : out[LL_TOTAL + ((b*64 + g*16 + c)*3 + band)*PLANE + p]
    #pragma unroll
    for (int g = 0; g < 4; g++) {
        size_t ch = (size_t)(b * 64 + g * 16 + c);
        {
            float s = sc[g];
            float4 o = make_float4(d0 * s, d1 * s, d2 * s, d3 * s);
            *reinterpret_cast<float4*>(out + ch * PLANE + p) = o;
        }
        #pragma unroll
        for (int band = 0; band < 3; band++) {
            float s = sc[4 + band * 4 + g];
            float4 o = make_float4(d0 * s, d1 * s, d2 * s, d3 * s);
            *reinterpret_cast<float4*>(out + LL_TOTAL + (ch * 3 + band) * PLANE + p) = o;
        }
    }
}

extern "C" void kernel_launch(void* const* d_in, const int* in_sizes, int n_in,
                              void* d_out, int out_size) {
    const float* image = (const float*)d_in[0];
    const float* gl    = (const float*)d_in[1];
    const float* gh    = (const float*)d_in[2];
    const float* fl    = (const float*)d_in[3];
    const float* fh    = (const float*)d_in[4];
    float* out = (float*)d_out;

    compute_scales_kernel<<<1, 32>>>(gl, gh, fl, fh);

    // total threads = B*C*HOUT*(WOUT/4) = 4*16*256*64 = 1,048,576
    const int threads = 256;
    const int blocks = (B_ * C_ * HOUT * (WOUT / 4)) / threads;  // 4096
    qwt_kernel<<<blocks, threads>>>(image, out);
}